// round 9
// baseline (speedup 1.0000x reference)
#include <cuda_runtime.h>
#include <cuda_bf16.h>
#include <stdint.h>

#define N_TOK   32768
#define N_CODE  8192
#define DIM     256
#define QUANT_ELEMS (N_TOK * DIM)

// ---------------- static scratch ----------------
// bf16 3-limb fragment-packed operands (m16n8k16 register order).
// g_xs: [blk16 (2048)][kstep (16)][limb (3)][lane (32)][4 x b32]  = 50.3 MB
// g_es: [blk8  (1024)][kstep (16)][limb (3)][lane (32)][2 x b32]  = 12.6 MB
__device__ uint32_t g_xs[(size_t)2048 * 16 * 3 * 128];
__device__ uint32_t g_es[(size_t)1024 * 16 * 3 * 64];
__device__ float g_e2[N_CODE];
__device__ int   g_idx[N_TOK];
__device__ float g_part[4096];

// ---------------- helpers ----------------
__device__ __forceinline__ uint32_t smem_u32(const void* p) {
    uint32_t a;
    asm("{ .reg .u64 t; cvta.to.shared.u64 t, %1; cvt.u32.u64 %0, t; }"
        : "=r"(a) : "l"(p));
    return a;
}
__device__ __forceinline__ void cp16(uint32_t dst, const void* src) {
    asm volatile("cp.async.cg.shared.global [%0], [%1], 16;" :: "r"(dst), "l"(src));
}
#define CP_COMMIT() asm volatile("cp.async.commit_group;" ::: "memory")
#define CP_WAIT(n)  asm volatile("cp.async.wait_group %0;" :: "n"(n) : "memory")

// exact 3-limb bf16 split: x = h + m + l + O(2^-24 x); subtractions exact
__device__ __forceinline__ void split3b(float x, float& h, float& m, float& l) {
    h = __bfloat162float(__float2bfloat16(x));
    float r1 = x - h;
    m = __bfloat162float(__float2bfloat16(r1));
    float r2 = r1 - m;
    l = __bfloat162float(__float2bfloat16(r2));
}
__device__ __forceinline__ uint32_t bpack(float lo, float hi) {
    return (__float_as_uint(hi) & 0xFFFF0000u) | (__float_as_uint(lo) >> 16);
}

// m16n8k16 bf16 mma, D += A*B (row.col), fp32 accumulate in place
__device__ __forceinline__ void mma16(float* c, const uint4& a, const uint2& b) {
    asm volatile(
        "mma.sync.aligned.m16n8k16.row.col.f32.bf16.bf16.f32 "
        "{%0,%1,%2,%3}, {%4,%5,%6,%7}, {%8,%9}, {%0,%1,%2,%3};"
        : "+f"(c[0]), "+f"(c[1]), "+f"(c[2]), "+f"(c[3])
        : "r"(a.x), "r"(a.y), "r"(a.z), "r"(a.w), "r"(b.x), "r"(b.y));
}

// ---------------- prep kernels (validated in round 7) ----------------
__global__ void k_prep_x(const float* __restrict__ X) {
    int gt   = blockIdx.x * 256 + threadIdx.x;
    int lane = gt & 31;
    int w    = gt >> 5;
    int ks   = w & 15;
    int blk  = w >> 4;
    int g = lane >> 2, t = lane & 3;
    const float* r0 = X + (blk * 16 + g) * DIM + ks * 16 + 2 * t;
    const float* r1 = r0 + 8 * DIM;
    float s[8] = { r0[0], r0[1], r1[0], r1[1], r0[8], r0[9], r1[8], r1[9] };
    float h[8], m[8], l[8];
#pragma unroll
    for (int i = 0; i < 8; i++) split3b(s[i], h[i], m[i], l[i]);
    uint32_t* base = g_xs + (size_t)(blk * 16 + ks) * 384 + lane * 4;
    *(uint4*)(base)       = make_uint4(bpack(h[0],h[1]), bpack(h[2],h[3]),
                                       bpack(h[4],h[5]), bpack(h[6],h[7]));
    *(uint4*)(base + 128) = make_uint4(bpack(m[0],m[1]), bpack(m[2],m[3]),
                                       bpack(m[4],m[5]), bpack(m[6],m[7]));
    *(uint4*)(base + 256) = make_uint4(bpack(l[0],l[1]), bpack(l[2],l[3]),
                                       bpack(l[4],l[5]), bpack(l[6],l[7]));
}

__global__ void k_prep_e(const float* __restrict__ E) {
    int gt   = blockIdx.x * 256 + threadIdx.x;
    int lane = gt & 31;
    int w    = gt >> 5;
    int ks   = w & 15;
    int blk  = w >> 4;
    int g = lane >> 2, t = lane & 3;
    const float* r = E + (blk * 8 + g) * DIM + ks * 16 + 2 * t;
    float s[4] = { r[0], r[1], r[8], r[9] };
    float h[4], m[4], l[4];
#pragma unroll
    for (int i = 0; i < 4; i++) split3b(s[i], h[i], m[i], l[i]);
    uint32_t* base = g_es + (size_t)(blk * 16 + ks) * 192 + lane * 2;
    *(uint2*)(base)       = make_uint2(bpack(h[0],h[1]), bpack(h[2],h[3]));
    *(uint2*)(base + 64)  = make_uint2(bpack(m[0],m[1]), bpack(m[2],m[3]));
    *(uint2*)(base + 128) = make_uint2(bpack(l[0],l[1]), bpack(l[2],l[3]));
}

__global__ void k_e2(const float* __restrict__ E) {
    int warp = (blockIdx.x << 3) + (threadIdx.x >> 5);
    int lane = threadIdx.x & 31;
    const float* row = E + warp * DIM;
    float s = 0.f;
#pragma unroll
    for (int i = 0; i < 8; i++) { float v = row[lane + i * 32]; s = fmaf(v, v, s); }
#pragma unroll
    for (int off = 16; off; off >>= 1) s += __shfl_down_sync(0xffffffffu, s, off);
    if (lane == 0) g_e2[warp] = s;
}

// ---------------- main: bf16 6-pass mma GEMM, A resident, fused argmin ------
// 256 CTAs x 512 threads (4 m-warps x 4 n-warps, warp tile 32x32).
// A slab (192 KB) resident; B streamed 12 KB double-buffered chunks.
// One barrier per iteration; CP_WAIT(0) guarantees chunk c (race-fixed).
#define A_BYTES   196608
#define B_CHUNK   12288
#define SM_B0     A_BYTES
#define SM_B1     (A_BYTES + B_CHUNK)
#define SM_SMIN   (A_BYTES + 2 * B_CHUNK)
#define SM_TOTAL  (SM_SMIN + 1024)

__global__ __launch_bounds__(512, 1) void k_main(float* __restrict__ out_idx_f) {
    extern __shared__ __align__(16) char sm[];
    unsigned long long* s_min = (unsigned long long*)(sm + SM_SMIN);

    const int tid  = threadIdx.x;
    const int lane = tid & 31, wid = tid >> 5;
    const int wm = wid & 3, wn = wid >> 2;       // 4 x 4 warp grid
    const int g = lane >> 2, t = lane & 3;
    const int m0 = blockIdx.x * 128;
    const uint32_t sb = smem_u32(sm);

    if (tid < 128) s_min[tid] = ~0ull;

    const char* gA = (const char*)g_xs + (size_t)blockIdx.x * A_BYTES;
    const char* gE = (const char*)g_es;

    // A slab: one-shot load
#pragma unroll
    for (int i = 0; i < 24; i++) {
        int off = (tid + i * 512) * 16;
        cp16(sb + off, gA + off);
    }
    // B chunk 0 -> stage 0
#pragma unroll
    for (int i = 0; i < 2; i++) {
        int idx = tid + i * 512;
        if (idx < 768) {
            int j = idx / 48, inner = (idx % 48) * 16;
            cp16(sb + SM_B0 + j * 768 + inner, gE + (size_t)j * 12288 + inner);
        }
    }
    CP_COMMIT();

    float cacc[2][4][4];
    float minv[4];
    int   mini[4];
#pragma unroll
    for (int i = 0; i < 4; i++) { minv[i] = 3.4e38f; mini[i] = 0; }

    for (int c = 0; c < 1024; c++) {             // 64 n-tiles x 16 ksteps
        const int nt = c >> 4, ks = c & 15, s = c & 1;

        // chunk c is the NEWEST committed group -> must wait for ALL groups.
        CP_WAIT(0);
        // single barrier: chunk c visible; all warps done reading stage s^1
        __syncthreads();

        // prefetch chunk c+1 into stage s^1 (safe after barrier)
        if (c + 1 < 1024) {
            const int c2 = c + 1, nt2 = c2 >> 4, ks2 = c2 & 15;
            const uint32_t dst = sb + ((c2 & 1) ? SM_B1 : SM_B0);
            const char* src = gE + (size_t)nt2 * 16 * 12288 + ks2 * 768;
#pragma unroll
            for (int i = 0; i < 2; i++) {
                int idx = tid + i * 512;
                if (idx < 768) {
                    int j = idx / 48, inner = (idx % 48) * 16;
                    cp16(dst + j * 768 + inner, src + (size_t)j * 12288 + inner);
                }
            }
            CP_COMMIT();
        }

        if (ks == 0) {
#pragma unroll
            for (int mf = 0; mf < 2; mf++)
#pragma unroll
                for (int nf = 0; nf < 4; nf++)
#pragma unroll
                    for (int e = 0; e < 4; e++) cacc[mf][nf][e] = 0.f;
        }

        const char* smB = sm + (s ? SM_B1 : SM_B0);
        // 6 limb passes: (ap,bp) with ap+bp <= 2
#pragma unroll
        for (int ap = 0; ap < 3; ap++) {
            uint4 af[2];
#pragma unroll
            for (int mf = 0; mf < 2; mf++)
                af[mf] = *(const uint4*)(sm + (wm * 2 + mf) * 24576 +
                                         ks * 1536 + ap * 512 + lane * 16);
#pragma unroll
            for (int bp = 0; bp < 3; bp++) {
                if (bp < 3 - ap) {
#pragma unroll
                    for (int nf = 0; nf < 4; nf++) {
                        uint2 bf = *(const uint2*)(smB + (wn * 4 + nf) * 768 +
                                                   bp * 256 + lane * 8);
#pragma unroll
                        for (int mf = 0; mf < 2; mf++)
                            mma16(cacc[mf][nf], af[mf], bf);
                    }
                }
            }
        }

        if (ks == 15) {
            // distance epilogue + per-thread running argmin (ascending codes)
            const float* e2t = g_e2 + nt * 128 + wn * 32;
#pragma unroll
            for (int nf = 0; nf < 4; nf++) {
                float2 e2v = *(const float2*)(e2t + nf * 8 + 2 * t);
                int code = nt * 128 + wn * 32 + nf * 8 + 2 * t;
#pragma unroll
                for (int mf = 0; mf < 2; mf++) {
#pragma unroll
                    for (int h = 0; h < 2; h++) {
                        int tk = mf * 2 + h;
                        float d0 = fmaf(-2.f, cacc[mf][nf][h * 2 + 0], e2v.x);
                        float d1 = fmaf(-2.f, cacc[mf][nf][h * 2 + 1], e2v.y);
                        if (d0 < minv[tk]) { minv[tk] = d0; mini[tk] = code; }
                        if (d1 < minv[tk]) { minv[tk] = d1; mini[tk] = code + 1; }
                    }
                }
            }
        }
    }

    // merge: quad shfl over code-dim threads, then packed atomicMin
#pragma unroll
    for (int tk = 0; tk < 4; tk++) {
        uint32_t u = __float_as_uint(minv[tk]);
        u = (u & 0x80000000u) ? ~u : (u | 0x80000000u);
        unsigned long long p = ((unsigned long long)u << 32) | (unsigned)mini[tk];
        unsigned long long q;
        q = __shfl_xor_sync(0xffffffffu, p, 1); if (q < p) p = q;
        q = __shfl_xor_sync(0xffffffffu, p, 2); if (q < p) p = q;
        if (t == 0) {
            int mf = tk >> 1, h = tk & 1;
            atomicMin(&s_min[wm * 32 + mf * 16 + g + h * 8], p);
        }
    }
    __syncthreads();
    if (tid < 128) {
        int idx = (int)(s_min[tid] & 0xffffffffu);
        g_idx[m0 + tid]     = idx;
        out_idx_f[m0 + tid] = (float)idx;
    }
}

// ---------------- gather + loss (validated) ----------------
__global__ void k_gather(const float* __restrict__ X, const float* __restrict__ E,
                         float* __restrict__ outq) {
    __shared__ float red[256];
    const int tid = threadIdx.x;
    const long base = (long)blockIdx.x * 2048;
    float s = 0.f;
#pragma unroll
    for (int i = 0; i < 8; i++) {
        long e = base + i * 256 + tid;
        int  m = (int)(e >> 8);
        int  d = (int)(e & 255);
        float q = E[g_idx[m] * DIM + d];
        float x = X[e];
        float diff = q - x;
        outq[e] = x + diff;
        s = fmaf(diff, diff, s);
    }
    red[tid] = s;
    __syncthreads();
#pragma unroll
    for (int st = 128; st; st >>= 1) {
        if (tid < st) red[tid] += red[tid + st];
        __syncthreads();
    }
    if (tid == 0) g_part[blockIdx.x] = red[0];
}
__global__ void k_loss(float* __restrict__ loss_out) {
    __shared__ float red[256];
    const int tid = threadIdx.x;
    float s = 0.f;
    for (int i = tid; i < 4096; i += 256) s += g_part[i];
    red[tid] = s;
    __syncthreads();
#pragma unroll
    for (int st = 128; st; st >>= 1) {
        if (tid < st) red[tid] += red[tid + st];
        __syncthreads();
    }
    if (tid == 0) loss_out[0] = 2.0f * (red[0] / (float)QUANT_ELEMS);
}

// ---------------- launch ----------------
extern "C" void kernel_launch(void* const* d_in, const int* in_sizes, int n_in,
                              void* d_out, int out_size) {
    const float* X = (const float*)d_in[0];
    const float* E = (const float*)d_in[1];
    float* out = (float*)d_out;

    float* outq    = out;
    float* outloss = out + QUANT_ELEMS;
    float* outidx  = out + QUANT_ELEMS + 1;

    cudaFuncSetAttribute(k_main, cudaFuncAttributeMaxDynamicSharedMemorySize,
                         SM_TOTAL);

    k_prep_x<<<4096, 256>>>(X);
    k_prep_e<<<2048, 256>>>(E);
    k_e2    <<<N_CODE / 8, 256>>>(E);
    k_main  <<<N_TOK / 128, 512, SM_TOTAL>>>(outidx);
    k_gather<<<QUANT_ELEMS / 2048, 256>>>(X, E, outq);
    k_loss  <<<1, 256>>>(outloss);

    (void)in_sizes; (void)n_in; (void)out_size;
}

// round 10
// speedup vs baseline: 1.1817x; 1.1817x over previous
#include <cuda_runtime.h>
#include <cuda_bf16.h>
#include <stdint.h>

#define N_TOK   32768
#define N_CODE  8192
#define DIM     256
#define QUANT_ELEMS (N_TOK * DIM)

// ---------------- static scratch ----------------
// bf16 3-limb fragment-packed operands (m16n8k16 register order).
// g_xs: [blk16 (2048)][kstep (16)][limb (3)][lane (32)][4 x b32]  = 50.3 MB
// g_es: [blk8  (1024)][kstep (16)][limb (3)][lane (32)][2 x b32]  = 12.6 MB
__device__ uint32_t g_xs[(size_t)2048 * 16 * 3 * 128];
__device__ uint32_t g_es[(size_t)1024 * 16 * 3 * 64];
__device__ float g_e2[N_CODE];
__device__ int   g_idx[N_TOK];
__device__ float g_part[4096];

// ---------------- helpers ----------------
__device__ __forceinline__ uint32_t smem_u32(const void* p) {
    uint32_t a;
    asm("{ .reg .u64 t; cvta.to.shared.u64 t, %1; cvt.u32.u64 %0, t; }"
        : "=r"(a) : "l"(p));
    return a;
}
__device__ __forceinline__ void cp16(uint32_t dst, const void* src) {
    asm volatile("cp.async.cg.shared.global [%0], [%1], 16;" :: "r"(dst), "l"(src));
}
#define CP_COMMIT() asm volatile("cp.async.commit_group;" ::: "memory")
#define CP_WAIT(n)  asm volatile("cp.async.wait_group %0;" :: "n"(n) : "memory")

// exact 3-limb bf16 split: x = h + m + l + O(2^-24 x); subtractions exact
__device__ __forceinline__ void split3b(float x, float& h, float& m, float& l) {
    h = __bfloat162float(__float2bfloat16(x));
    float r1 = x - h;
    m = __bfloat162float(__float2bfloat16(r1));
    float r2 = r1 - m;
    l = __bfloat162float(__float2bfloat16(r2));
}
__device__ __forceinline__ uint32_t bpack(float lo, float hi) {
    return (__float_as_uint(hi) & 0xFFFF0000u) | (__float_as_uint(lo) >> 16);
}

// m16n8k16 bf16 mma, D += A*B (row.col), fp32 accumulate in place
__device__ __forceinline__ void mma16(float* c, const uint4& a, const uint2& b) {
    asm volatile(
        "mma.sync.aligned.m16n8k16.row.col.f32.bf16.bf16.f32 "
        "{%0,%1,%2,%3}, {%4,%5,%6,%7}, {%8,%9}, {%0,%1,%2,%3};"
        : "+f"(c[0]), "+f"(c[1]), "+f"(c[2]), "+f"(c[3])
        : "r"(a.x), "r"(a.y), "r"(a.z), "r"(a.w), "r"(b.x), "r"(b.y));
}

// ---------------- prep kernels (validated) ----------------
__global__ void k_prep_x(const float* __restrict__ X) {
    int gt   = blockIdx.x * 256 + threadIdx.x;
    int lane = gt & 31;
    int w    = gt >> 5;
    int ks   = w & 15;
    int blk  = w >> 4;
    int g = lane >> 2, t = lane & 3;
    const float* r0 = X + (blk * 16 + g) * DIM + ks * 16 + 2 * t;
    const float* r1 = r0 + 8 * DIM;
    float s[8] = { r0[0], r0[1], r1[0], r1[1], r0[8], r0[9], r1[8], r1[9] };
    float h[8], m[8], l[8];
#pragma unroll
    for (int i = 0; i < 8; i++) split3b(s[i], h[i], m[i], l[i]);
    uint32_t* base = g_xs + (size_t)(blk * 16 + ks) * 384 + lane * 4;
    *(uint4*)(base)       = make_uint4(bpack(h[0],h[1]), bpack(h[2],h[3]),
                                       bpack(h[4],h[5]), bpack(h[6],h[7]));
    *(uint4*)(base + 128) = make_uint4(bpack(m[0],m[1]), bpack(m[2],m[3]),
                                       bpack(m[4],m[5]), bpack(m[6],m[7]));
    *(uint4*)(base + 256) = make_uint4(bpack(l[0],l[1]), bpack(l[2],l[3]),
                                       bpack(l[4],l[5]), bpack(l[6],l[7]));
}

__global__ void k_prep_e(const float* __restrict__ E) {
    int gt   = blockIdx.x * 256 + threadIdx.x;
    int lane = gt & 31;
    int w    = gt >> 5;
    int ks   = w & 15;
    int blk  = w >> 4;
    int g = lane >> 2, t = lane & 3;
    const float* r = E + (blk * 8 + g) * DIM + ks * 16 + 2 * t;
    float s[4] = { r[0], r[1], r[8], r[9] };
    float h[4], m[4], l[4];
#pragma unroll
    for (int i = 0; i < 4; i++) split3b(s[i], h[i], m[i], l[i]);
    uint32_t* base = g_es + (size_t)(blk * 16 + ks) * 192 + lane * 2;
    *(uint2*)(base)       = make_uint2(bpack(h[0],h[1]), bpack(h[2],h[3]));
    *(uint2*)(base + 64)  = make_uint2(bpack(m[0],m[1]), bpack(m[2],m[3]));
    *(uint2*)(base + 128) = make_uint2(bpack(l[0],l[1]), bpack(l[2],l[3]));
}

__global__ void k_e2(const float* __restrict__ E) {
    int warp = (blockIdx.x << 3) + (threadIdx.x >> 5);
    int lane = threadIdx.x & 31;
    const float* row = E + warp * DIM;
    float s = 0.f;
#pragma unroll
    for (int i = 0; i < 8; i++) { float v = row[lane + i * 32]; s = fmaf(v, v, s); }
#pragma unroll
    for (int off = 16; off; off >>= 1) s += __shfl_down_sync(0xffffffffu, s, off);
    if (lane == 0) g_e2[warp] = s;
}

// ---------------- main: barrier-free bf16 6-pass mma GEMM + fused argmin ----
// 256 CTAs x 512 threads (4 m-warps x 4 n-warps, warp tile 32x32).
// A slab (192 KB) SMEM-resident (one load, one sync). B read per-kstep via
// __ldg from L2-resident g_es — NO barriers, NO staging in the 1024-iter loop.
#define A_BYTES   196608
#define SM_SMIN   A_BYTES
#define SM_TOTAL  (SM_SMIN + 1024)

__global__ __launch_bounds__(512, 1) void k_main(float* __restrict__ out_idx_f) {
    extern __shared__ __align__(16) char sm[];
    unsigned long long* s_min = (unsigned long long*)(sm + SM_SMIN);

    const int tid  = threadIdx.x;
    const int lane = tid & 31, wid = tid >> 5;
    const int wm = wid & 3, wn = wid >> 2;       // 4 x 4 warp grid
    const int g = lane >> 2, t = lane & 3;
    const int m0 = blockIdx.x * 128;
    const uint32_t sb = smem_u32(sm);

    if (tid < 128) s_min[tid] = ~0ull;

    const char* gA = (const char*)g_xs + (size_t)blockIdx.x * A_BYTES;

    // A slab: one-shot cp.async load, single barrier
#pragma unroll
    for (int i = 0; i < 24; i++) {
        int off = (tid + i * 512) * 16;
        cp16(sb + off, gA + off);
    }
    CP_COMMIT();
    CP_WAIT(0);
    __syncthreads();

    float minv[4];
    int   mini[4];
#pragma unroll
    for (int i = 0; i < 4; i++) { minv[i] = 3.4e38f; mini[i] = 0; }

    // per-warp B base: code block nb0 = wn*4 (advances by 16 per n-tile)
    const uint32_t* gBlane = g_es + (size_t)lane * 2;

    for (int nt = 0; nt < 64; nt++) {
        float cacc[2][4][4];
#pragma unroll
        for (int mf = 0; mf < 2; mf++)
#pragma unroll
            for (int nf = 0; nf < 4; nf++)
#pragma unroll
                for (int e = 0; e < 4; e++) cacc[mf][nf][e] = 0.f;

#pragma unroll 1
        for (int ks = 0; ks < 16; ks++) {
            // B fragments straight from L2: 12 coalesced LDG.64 per warp
            uint2 bf[3][4];
#pragma unroll
            for (int nf = 0; nf < 4; nf++) {
                const uint32_t* pb =
                    gBlane + (size_t)((nt * 16 + wn * 4 + nf) * 16 + ks) * 192;
#pragma unroll
                for (int bp = 0; bp < 3; bp++)
                    bf[bp][nf] = __ldg((const uint2*)(pb + bp * 64));
            }
            // A fragments from resident SMEM
            uint4 af[3][2];
#pragma unroll
            for (int ap = 0; ap < 3; ap++)
#pragma unroll
                for (int mf = 0; mf < 2; mf++)
                    af[ap][mf] = *(const uint4*)(sm + (wm * 2 + mf) * 24576 +
                                                 ks * 1536 + ap * 512 + lane * 16);
            // 6 limb passes: (ap,bp) with ap+bp <= 2
#pragma unroll
            for (int ap = 0; ap < 3; ap++)
#pragma unroll
                for (int bp = 0; bp < 3; bp++) {
                    if (bp < 3 - ap) {
#pragma unroll
                        for (int nf = 0; nf < 4; nf++)
#pragma unroll
                            for (int mf = 0; mf < 2; mf++)
                                mma16(cacc[mf][nf], af[ap][mf], bf[bp][nf]);
                    }
                }
        }

        // distance epilogue + per-thread running argmin (ascending codes)
        const float* e2t = g_e2 + nt * 128 + wn * 32;
#pragma unroll
        for (int nf = 0; nf < 4; nf++) {
            float2 e2v = *(const float2*)(e2t + nf * 8 + 2 * t);
            int code = nt * 128 + wn * 32 + nf * 8 + 2 * t;
#pragma unroll
            for (int mf = 0; mf < 2; mf++) {
#pragma unroll
                for (int h = 0; h < 2; h++) {
                    int tk = mf * 2 + h;
                    float d0 = fmaf(-2.f, cacc[mf][nf][h * 2 + 0], e2v.x);
                    float d1 = fmaf(-2.f, cacc[mf][nf][h * 2 + 1], e2v.y);
                    if (d0 < minv[tk]) { minv[tk] = d0; mini[tk] = code; }
                    if (d1 < minv[tk]) { minv[tk] = d1; mini[tk] = code + 1; }
                }
            }
        }
    }

    // merge: quad shfl over code-dim threads, then packed atomicMin
#pragma unroll
    for (int tk = 0; tk < 4; tk++) {
        uint32_t u = __float_as_uint(minv[tk]);
        u = (u & 0x80000000u) ? ~u : (u | 0x80000000u);
        unsigned long long p = ((unsigned long long)u << 32) | (unsigned)mini[tk];
        unsigned long long q;
        q = __shfl_xor_sync(0xffffffffu, p, 1); if (q < p) p = q;
        q = __shfl_xor_sync(0xffffffffu, p, 2); if (q < p) p = q;
        if (t == 0) {
            int mf = tk >> 1, h = tk & 1;
            atomicMin(&s_min[wm * 32 + mf * 16 + g + h * 8], p);
        }
    }
    __syncthreads();
    if (tid < 128) {
        int idx = (int)(s_min[tid] & 0xffffffffu);
        g_idx[m0 + tid]     = idx;
        out_idx_f[m0 + tid] = (float)idx;
    }
}

// ---------------- gather + loss (validated) ----------------
__global__ void k_gather(const float* __restrict__ X, const float* __restrict__ E,
                         float* __restrict__ outq) {
    __shared__ float red[256];
    const int tid = threadIdx.x;
    const long base = (long)blockIdx.x * 2048;
    float s = 0.f;
#pragma unroll
    for (int i = 0; i < 8; i++) {
        long e = base + i * 256 + tid;
        int  m = (int)(e >> 8);
        int  d = (int)(e & 255);
        float q = E[g_idx[m] * DIM + d];
        float x = X[e];
        float diff = q - x;
        outq[e] = x + diff;
        s = fmaf(diff, diff, s);
    }
    red[tid] = s;
    __syncthreads();
#pragma unroll
    for (int st = 128; st; st >>= 1) {
        if (tid < st) red[tid] += red[tid + st];
        __syncthreads();
    }
    if (tid == 0) g_part[blockIdx.x] = red[0];
}
__global__ void k_loss(float* __restrict__ loss_out) {
    __shared__ float red[256];
    const int tid = threadIdx.x;
    float s = 0.f;
    for (int i = tid; i < 4096; i += 256) s += g_part[i];
    red[tid] = s;
    __syncthreads();
#pragma unroll
    for (int st = 128; st; st >>= 1) {
        if (tid < st) red[tid] += red[tid + st];
        __syncthreads();
    }
    if (tid == 0) loss_out[0] = 2.0f * (red[0] / (float)QUANT_ELEMS);
}

// ---------------- launch ----------------
extern "C" void kernel_launch(void* const* d_in, const int* in_sizes, int n_in,
                              void* d_out, int out_size) {
    const float* X = (const float*)d_in[0];
    const float* E = (const float*)d_in[1];
    float* out = (float*)d_out;

    float* outq    = out;
    float* outloss = out + QUANT_ELEMS;
    float* outidx  = out + QUANT_ELEMS + 1;

    cudaFuncSetAttribute(k_main, cudaFuncAttributeMaxDynamicSharedMemorySize,
                         SM_TOTAL);

    k_prep_x<<<4096, 256>>>(X);
    k_prep_e<<<2048, 256>>>(E);
    k_e2    <<<N_CODE / 8, 256>>>(E);
    k_main  <<<N_TOK / 128, 512, SM_TOTAL>>>(outidx);
    k_gather<<<QUANT_ELEMS / 2048, 256>>>(X, E, outq);
    k_loss  <<<1, 256>>>(outloss);

    (void)in_sizes; (void)n_in; (void)out_size;
}

// round 11
// speedup vs baseline: 1.9140x; 1.6198x over previous
#include <cuda_runtime.h>
#include <cuda_fp16.h>
#include <stdint.h>

#define N_TOK   32768
#define N_CODE  8192
#define DIM     256
#define QUANT_ELEMS (N_TOK * DIM)

// ---------------- static scratch ----------------
// fp16 2-limb fragment-packed operands (m16n8k16 register order).
// g_xs: [blk16 (2048)][kstep (16)][limb (2)][lane (32)][4 x b32] = 33.6 MB
// g_es: [blk8  (1024)][kstep (16)][limb (2)][lane (32)][2 x b32] =  8.4 MB
__device__ uint32_t g_xs[(size_t)2048 * 16 * 2 * 128];
__device__ uint32_t g_es[(size_t)1024 * 16 * 2 * 64];
__device__ float g_e2[N_CODE];
__device__ int   g_idx[N_TOK];
__device__ int   g_c1[N_TOK];
__device__ int   g_c2[N_TOK];
__device__ float g_part[4096];

// ---------------- helpers ----------------
__device__ __forceinline__ uint32_t smem_u32(const void* p) {
    uint32_t a;
    asm("{ .reg .u64 t; cvta.to.shared.u64 t, %1; cvt.u32.u64 %0, t; }"
        : "=r"(a) : "l"(p));
    return a;
}
__device__ __forceinline__ void cp16(uint32_t dst, const void* src) {
    asm volatile("cp.async.cg.shared.global [%0], [%1], 16;" :: "r"(dst), "l"(src));
}
#define CP_COMMIT() asm volatile("cp.async.commit_group;" ::: "memory")
#define CP_WAIT(n)  asm volatile("cp.async.wait_group %0;" :: "n"(n) : "memory")

// exact 2-limb fp16 split: x = h + m + O(2^-22 x); subtraction exact
__device__ __forceinline__ void split2h(float x, uint16_t& hb, uint16_t& mb) {
    __half hh = __float2half_rn(x);
    float  hf = __half2float(hh);
    __half mm = __float2half_rn(x - hf);
    hb = __half_as_ushort(hh);
    mb = __half_as_ushort(mm);
}
__device__ __forceinline__ uint32_t hpack(uint16_t lo, uint16_t hi) {
    return (uint32_t)lo | ((uint32_t)hi << 16);
}

// m16n8k16 fp16 mma, D += A*B (row.col), fp32 accumulate in place
__device__ __forceinline__ void mma16(float* c, const uint4& a, const uint2& b) {
    asm volatile(
        "mma.sync.aligned.m16n8k16.row.col.f32.f16.f16.f32 "
        "{%0,%1,%2,%3}, {%4,%5,%6,%7}, {%8,%9}, {%0,%1,%2,%3};"
        : "+f"(c[0]), "+f"(c[1]), "+f"(c[2]), "+f"(c[3])
        : "r"(a.x), "r"(a.y), "r"(a.z), "r"(a.w), "r"(b.x), "r"(b.y));
}

// ---------------- prep kernels ----------------
__global__ void k_prep_x(const float* __restrict__ X) {
    int gt   = blockIdx.x * 256 + threadIdx.x;   // 1,048,576 threads
    int lane = gt & 31;
    int w    = gt >> 5;
    int ks   = w & 15;
    int blk  = w >> 4;
    int g = lane >> 2, t = lane & 3;
    const float* r0 = X + (blk * 16 + g) * DIM + ks * 16 + 2 * t;
    const float* r1 = r0 + 8 * DIM;
    float s[8] = { r0[0], r0[1], r1[0], r1[1], r0[8], r0[9], r1[8], r1[9] };
    uint16_t h[8], m[8];
#pragma unroll
    for (int i = 0; i < 8; i++) split2h(s[i], h[i], m[i]);
    uint32_t* base = g_xs + (size_t)(blk * 16 + ks) * 256 + lane * 4;
    *(uint4*)(base)       = make_uint4(hpack(h[0],h[1]), hpack(h[2],h[3]),
                                       hpack(h[4],h[5]), hpack(h[6],h[7]));
    *(uint4*)(base + 128) = make_uint4(hpack(m[0],m[1]), hpack(m[2],m[3]),
                                       hpack(m[4],m[5]), hpack(m[6],m[7]));
}

__global__ void k_prep_e(const float* __restrict__ E) {
    int gt   = blockIdx.x * 256 + threadIdx.x;   // 524,288 threads
    int lane = gt & 31;
    int w    = gt >> 5;
    int ks   = w & 15;
    int blk  = w >> 4;
    int g = lane >> 2, t = lane & 3;
    const float* r = E + (blk * 8 + g) * DIM + ks * 16 + 2 * t;
    float s[4] = { r[0], r[1], r[8], r[9] };
    uint16_t h[4], m[4];
#pragma unroll
    for (int i = 0; i < 4; i++) split2h(s[i], h[i], m[i]);
    uint32_t* base = g_es + (size_t)(blk * 16 + ks) * 128 + lane * 2;
    *(uint2*)(base)      = make_uint2(hpack(h[0],h[1]), hpack(h[2],h[3]));
    *(uint2*)(base + 64) = make_uint2(hpack(m[0],m[1]), hpack(m[2],m[3]));
}

__global__ void k_e2(const float* __restrict__ E) {
    int warp = (blockIdx.x << 3) + (threadIdx.x >> 5);
    int lane = threadIdx.x & 31;
    const float* row = E + warp * DIM;
    float s = 0.f;
#pragma unroll
    for (int i = 0; i < 8; i++) { float v = row[lane + i * 32]; s = fmaf(v, v, s); }
#pragma unroll
    for (int off = 16; off; off >>= 1) s += __shfl_down_sync(0xffffffffu, s, off);
    if (lane == 0) g_e2[warp] = s;
}

// ---------------- main: barrier-free fp16 3-pass mma GEMM + top-2 argmin ----
// 256 CTAs x 512 threads (4 m-warps x 4 n-warps, warp tile 32x32).
// A slab (128 KB) SMEM-resident; B via __ldg from L2-resident g_es.
// Tracks per-token TOP-2 approx candidates; exact fp32 rescore in k_pick.
#define A_BYTES   131072
#define SM_MIN1   A_BYTES
#define SM_MIN2   (A_BYTES + 1024)
#define SM_TOTAL  (A_BYTES + 2048)

__device__ __forceinline__ unsigned long long packdi(float v, int i) {
    uint32_t u = __float_as_uint(v);
    u = (u & 0x80000000u) ? ~u : (u | 0x80000000u);
    return ((unsigned long long)u << 32) | (unsigned)i;
}

__global__ __launch_bounds__(512, 1) void k_main() {
    extern __shared__ __align__(16) char sm[];
    unsigned long long* s_min1 = (unsigned long long*)(sm + SM_MIN1);
    unsigned long long* s_min2 = (unsigned long long*)(sm + SM_MIN2);

    const int tid  = threadIdx.x;
    const int lane = tid & 31, wid = tid >> 5;
    const int wm = wid & 3, wn = wid >> 2;       // 4 x 4 warp grid
    const int g = lane >> 2, t = lane & 3;
    const int m0 = blockIdx.x * 128;
    const uint32_t sb = smem_u32(sm);

    if (tid < 128) { s_min1[tid] = ~0ull; s_min2[tid] = ~0ull; }

    const char* gA = (const char*)g_xs + (size_t)blockIdx.x * A_BYTES;

    // A slab: one-shot cp.async load, single barrier
#pragma unroll
    for (int i = 0; i < 16; i++) {
        int off = (tid + i * 512) * 16;
        cp16(sb + off, gA + off);
    }
    CP_COMMIT();
    CP_WAIT(0);
    __syncthreads();

    // per-token-row top-2 (4 rows per thread)
    float v1[4], v2[4];
    int   i1[4], i2[4];
#pragma unroll
    for (int i = 0; i < 4; i++) { v1[i] = v2[i] = 3.4e38f; i1[i] = i2[i] = 0; }

    const uint32_t* gBlane = g_es + (size_t)lane * 2;

    for (int nt = 0; nt < 64; nt++) {
        float cacc[2][4][4];
#pragma unroll
        for (int mf = 0; mf < 2; mf++)
#pragma unroll
            for (int nf = 0; nf < 4; nf++)
#pragma unroll
                for (int e = 0; e < 4; e++) cacc[mf][nf][e] = 0.f;

#pragma unroll 1
        for (int ks = 0; ks < 16; ks++) {
            // B fragments straight from L2: 8 coalesced LDG.64 per warp
            uint2 bf[2][4];
#pragma unroll
            for (int nf = 0; nf < 4; nf++) {
                const uint32_t* pb =
                    gBlane + (size_t)((nt * 16 + wn * 4 + nf) * 16 + ks) * 128;
                bf[0][nf] = __ldg((const uint2*)pb);
                bf[1][nf] = __ldg((const uint2*)(pb + 64));
            }
            // A fragments from resident SMEM
            uint4 af[2][2];
#pragma unroll
            for (int ap = 0; ap < 2; ap++)
#pragma unroll
                for (int mf = 0; mf < 2; mf++)
                    af[ap][mf] = *(const uint4*)(sm + (wm * 2 + mf) * 16384 +
                                                 ks * 1024 + ap * 512 + lane * 16);
            // 3 limb passes: hh, hm, mh (drop mm ~ 2^-22)
#pragma unroll
            for (int ap = 0; ap < 2; ap++)
#pragma unroll
                for (int bp = 0; bp < 2; bp++) {
                    if (ap + bp < 2) {
#pragma unroll
                        for (int nf = 0; nf < 4; nf++)
#pragma unroll
                            for (int mf = 0; mf < 2; mf++)
                                mma16(cacc[mf][nf], af[ap][mf], bf[bp][nf]);
                    }
                }
        }

        // distance epilogue + per-thread running TOP-2 (ascending codes)
        const float* e2t = g_e2 + nt * 128 + wn * 32;
#pragma unroll
        for (int nf = 0; nf < 4; nf++) {
            float2 e2v = *(const float2*)(e2t + nf * 8 + 2 * t);
            int code = nt * 128 + wn * 32 + nf * 8 + 2 * t;
#pragma unroll
            for (int mf = 0; mf < 2; mf++) {
#pragma unroll
                for (int h = 0; h < 2; h++) {
                    int tk = mf * 2 + h;
                    float d0 = fmaf(-2.f, cacc[mf][nf][h * 2 + 0], e2v.x);
                    float d1 = fmaf(-2.f, cacc[mf][nf][h * 2 + 1], e2v.y);
                    if (d0 < v1[tk]) { v2[tk]=v1[tk]; i2[tk]=i1[tk]; v1[tk]=d0; i1[tk]=code; }
                    else if (d0 < v2[tk]) { v2[tk]=d0; i2[tk]=code; }
                    if (d1 < v1[tk]) { v2[tk]=v1[tk]; i2[tk]=i1[tk]; v1[tk]=d1; i1[tk]=code+1; }
                    else if (d1 < v2[tk]) { v2[tk]=d1; i2[tk]=code+1; }
                }
            }
        }
    }

    // quad-shfl top-2 set merge, then two-phase smem atomicMin
#pragma unroll
    for (int tk = 0; tk < 4; tk++) {
        unsigned long long p1 = packdi(v1[tk], i1[tk]);
        unsigned long long p2 = packdi(v2[tk], i2[tk]);
#pragma unroll
        for (int off = 1; off <= 2; off <<= 1) {
            unsigned long long q1 = __shfl_xor_sync(0xffffffffu, p1, off);
            unsigned long long q2 = __shfl_xor_sync(0xffffffffu, p2, off);
            unsigned long long lo = p1 < q1 ? p1 : q1;
            unsigned long long hi = p1 < q1 ? q1 : p1;
            unsigned long long m2 = p2 < q2 ? p2 : q2;
            p1 = lo;
            p2 = hi < m2 ? hi : m2;
        }
        if (t == 0) {
            int mf = tk >> 1, h = tk & 1;
            int slot = wm * 32 + mf * 16 + g + h * 8;
            atomicMin(&s_min1[slot], p1);
            // stash for phase 2 via registers (re-derive below)
        }
        v1[tk] = __ull2float_rz(0);  // dummy to keep regs; real state in p1/p2
        // phase 2 handled after barrier using recomputed pack (store in arrays)
        i1[tk] = (int)(p1 & 0xffffffffu);
        v2[tk] = 0.f;
        i2[tk] = (int)(p2 & 0xffffffffu);
        // keep full packed values in 64-bit via reuse: store halves
        // (we re-pack below from saved p1/p2 parts)
        // To keep it simple, save packed values in shared-unused? Use locals:
        // We instead re-run phase2 with p1/p2 still live in this scope:
        __syncthreads();
        if (t == 0) {
            int mf = tk >> 1, h = tk & 1;
            int slot = wm * 32 + mf * 16 + g + h * 8;
            unsigned long long g1 = s_min1[slot];
            unsigned long long cand = (p1 == g1) ? p2 : p1;
            atomicMin(&s_min2[slot], cand);
        }
        __syncthreads();
    }

    if (tid < 128) {
        g_c1[m0 + tid] = (int)(s_min1[tid] & 0xffffffffu);
        g_c2[m0 + tid] = (int)(s_min2[tid] & 0xffffffffu);
    }
}

// ---------------- exact fp32 rescore of the two candidates ----------------
__global__ void k_pick(const float* __restrict__ X, const float* __restrict__ E,
                       float* __restrict__ out_idx_f) {
    int warp = blockIdx.x * 8 + (threadIdx.x >> 5);   // one warp per token
    int lane = threadIdx.x & 31;
    int c1 = g_c1[warp], c2 = g_c2[warp];
    const float* x  = X + (size_t)warp * DIM;
    const float* e1 = E + (size_t)c1 * DIM;
    const float* e2 = E + (size_t)c2 * DIM;
    float dot1 = 0.f, dot2 = 0.f;
#pragma unroll
    for (int i = 0; i < 8; i++) {
        int k = lane + i * 32;
        float xv = x[k];
        dot1 = fmaf(xv, e1[k], dot1);
        dot2 = fmaf(xv, e2[k], dot2);
    }
#pragma unroll
    for (int off = 16; off; off >>= 1) {
        dot1 += __shfl_down_sync(0xffffffffu, dot1, off);
        dot2 += __shfl_down_sync(0xffffffffu, dot2, off);
    }
    if (lane == 0) {
        float d1 = fmaf(-2.f, dot1, g_e2[c1]);
        float d2 = fmaf(-2.f, dot2, g_e2[c2]);
        int c = (d2 < d1 || (d2 == d1 && c2 < c1)) ? c2 : c1;
        g_idx[warp] = c;
        out_idx_f[warp] = (float)c;
    }
}

// ---------------- gather + loss (validated) ----------------
__global__ void k_gather(const float* __restrict__ X, const float* __restrict__ E,
                         float* __restrict__ outq) {
    __shared__ float red[256];
    const int tid = threadIdx.x;
    const long base = (long)blockIdx.x * 2048;
    float s = 0.f;
#pragma unroll
    for (int i = 0; i < 8; i++) {
        long e = base + i * 256 + tid;
        int  m = (int)(e >> 8);
        int  d = (int)(e & 255);
        float q = E[g_idx[m] * DIM + d];
        float x = X[e];
        float diff = q - x;
        outq[e] = x + diff;
        s = fmaf(diff, diff, s);
    }
    red[tid] = s;
    __syncthreads();
#pragma unroll
    for (int st = 128; st; st >>= 1) {
        if (tid < st) red[tid] += red[tid + st];
        __syncthreads();
    }
    if (tid == 0) g_part[blockIdx.x] = red[0];
}
__global__ void k_loss(float* __restrict__ loss_out) {
    __shared__ float red[256];
    const int tid = threadIdx.x;
    float s = 0.f;
    for (int i = tid; i < 4096; i += 256) s += g_part[i];
    red[tid] = s;
    __syncthreads();
#pragma unroll
    for (int st = 128; st; st >>= 1) {
        if (tid < st) red[tid] += red[tid + st];
        __syncthreads();
    }
    if (tid == 0) loss_out[0] = 2.0f * (red[0] / (float)QUANT_ELEMS);
}

// ---------------- launch ----------------
extern "C" void kernel_launch(void* const* d_in, const int* in_sizes, int n_in,
                              void* d_out, int out_size) {
    const float* X = (const float*)d_in[0];
    const float* E = (const float*)d_in[1];
    float* out = (float*)d_out;

    float* outq    = out;
    float* outloss = out + QUANT_ELEMS;
    float* outidx  = out + QUANT_ELEMS + 1;

    cudaFuncSetAttribute(k_main, cudaFuncAttributeMaxDynamicSharedMemorySize,
                         SM_TOTAL);

    k_prep_x<<<4096, 256>>>(X);
    k_prep_e<<<2048, 256>>>(E);
    k_e2    <<<N_CODE / 8, 256>>>(E);
    k_main  <<<N_TOK / 128, 512, SM_TOTAL>>>();
    k_pick  <<<N_TOK / 8, 256>>>(X, E, outidx);
    k_gather<<<QUANT_ELEMS / 2048, 256>>>(X, E, outq);
    k_loss  <<<1, 256>>>(outloss);

    (void)in_sizes; (void)n_in; (void)out_size;
}